// round 2
// baseline (speedup 1.0000x reference)
#include <cuda_runtime.h>
#include <cstdint>

#define B_  64
#define T_  2048
#define I_  256
#define H_  256
#define G3_ 768

// 402 MB scratch for precomputed input gates: layout [t][b][768]
__device__ float g_Gi[(size_t)B_ * T_ * G3_];

// ======================= Phase 1: Gi = x @ W_ih^T + b_ih =======================
#define BM 128
#define BN 64
#define BK 32
#define PAD 36

__global__ __launch_bounds__(256) void gi_gemm(
    const float* __restrict__ x, const float* __restrict__ W_ih,
    const float* __restrict__ b_ih, const int* __restrict__ lengths)
{
    const int m0    = blockIdx.x * BM;        // row = b*T + t
    const int batch = m0 >> 11;               // 2048 rows per batch, 128 | 2048
    const int t0    = m0 & (T_ - 1);
    if (t0 >= __ldg(&lengths[batch])) return; // whole tile masked -> skip
    const int n0 = blockIdx.y * BN;

    __shared__ float As[BM][PAD];
    __shared__ float Bs[BN][PAD];

    const int tid = threadIdx.x;
    const int tx = tid & 15, ty = tid >> 4;   // 16 x 16 -> thread tile 8(m) x 4(n)

    float acc[8][4];
#pragma unroll
    for (int i = 0; i < 8; i++)
#pragma unroll
        for (int c = 0; c < 4; c++) acc[i][c] = 0.f;

    for (int kt = 0; kt < I_; kt += BK) {
#pragma unroll
        for (int j = 0; j < 4; j++) {
            int idx = tid + j * 256;
            int row = idx >> 3, kp = idx & 7;
            float4 v = *(const float4*)&x[(size_t)(m0 + row) * I_ + kt + kp * 4];
            *(float4*)&As[row][kp * 4] = v;
        }
#pragma unroll
        for (int j = 0; j < 2; j++) {
            int idx = tid + j * 256;
            int row = idx >> 3, kp = idx & 7;
            float4 v = *(const float4*)&W_ih[(size_t)(n0 + row) * I_ + kt + kp * 4];
            *(float4*)&Bs[row][kp * 4] = v;
        }
        __syncthreads();
#pragma unroll
        for (int k = 0; k < BK; k++) {
            float a[8], b[4];
#pragma unroll
            for (int i = 0; i < 8; i++) a[i] = As[ty * 8 + i][k];
#pragma unroll
            for (int c = 0; c < 4; c++) b[c] = Bs[tx * 4 + c][k];
#pragma unroll
            for (int i = 0; i < 8; i++)
#pragma unroll
                for (int c = 0; c < 4; c++) acc[i][c] += a[i] * b[c];
        }
        __syncthreads();
    }

#pragma unroll
    for (int i = 0; i < 8; i++) {
        int t = t0 + ty * 8 + i;
        int n = n0 + tx * 4;
        float4 v;
        v.x = acc[i][0] + b_ih[n + 0];
        v.y = acc[i][1] + b_ih[n + 1];
        v.z = acc[i][2] + b_ih[n + 2];
        v.w = acc[i][3] + b_ih[n + 3];
        *(float4*)&g_Gi[((size_t)t * B_ + batch) * G3_ + n] = v;
    }
}

// ======================= Phase 2: recurrence =======================
// 16 clusters of 8 CTAs. Cluster c handles batches {4c..4c+3}.
// CTA rank r owns H-columns [r*32, r*32+32) for all 3 gates:
//   slice rows: row = g*32 + jj  ->  global W_hh row g*256 + r*32 + jj  (96 rows)
// W slice lives entirely in REGISTERS: thread (row, k8) holds
// W[grow][k8*32 .. k8*32+31] pre-packed as 16 x f32x2 pairs.
// h (4 batches x 256, fp32) replicated in every CTA's SMEM, double-buffered,
// k8-rotated swizzle for conflict-free double2 loads.
// Per step: matvec (fma.rn.f32x2) -> 3-stage bfly reduce -> gates (128 thr)
// -> DSMEM broadcast of own 32-col slice -> one cluster barrier.

#define REC_THREADS 768

__device__ __forceinline__ float sigm(float v) { return 1.f / (1.f + __expf(-v)); }

__device__ __forceinline__ unsigned long long fma2(unsigned long long a,
                                                   unsigned long long b,
                                                   unsigned long long c) {
    unsigned long long d;
    asm("fma.rn.f32x2 %0, %1, %2, %3;" : "=l"(d) : "l"(a), "l"(b), "l"(c));
    return d;
}
__device__ __forceinline__ unsigned long long packf2(float lo, float hi) {
    unsigned long long d;
    asm("mov.b64 %0, {%1, %2};" : "=l"(d) : "f"(lo), "f"(hi));
    return d;
}
__device__ __forceinline__ float unpack_sum(unsigned long long v) {
    float lo, hi;
    asm("mov.b64 {%0, %1}, %2;" : "=f"(lo), "=f"(hi) : "l"(v));
    return lo + hi;
}
// swizzled float index within one batch's 256-col h row (k8-rotation of float4 slots)
__device__ __forceinline__ int hswiz(int c) {
    int k8c  = c >> 5;
    int slot = (((c >> 2) & 7) + k8c) & 7;
    return k8c * 32 + slot * 4 + (c & 3);
}

__global__ void __cluster_dims__(8, 1, 1) __launch_bounds__(REC_THREADS, 1)
gru_rec(const float* __restrict__ att, const int* __restrict__ lengths,
        const float* __restrict__ W_hh, const float* __restrict__ b_hh,
        float* __restrict__ out)
{
    __shared__ alignas(16) float hb[2][4][256];   // [buf][batch][col] (swizzled cols)
    __shared__ float ghsh[4][96];                 // [batch][slice row]

    uint32_t rank;
    asm("mov.u32 %0, %%cluster_ctarank;" : "=r"(rank));
    const int cid = blockIdx.x >> 3;
    const int b0  = cid * 4;

    const int tid = threadIdx.x;
    const int row = tid >> 3;          // 0..95 : g = row>>5, jj = row&31
    const int k8  = tid & 7;           // k-eighth: k in [k8*32, k8*32+32)

    // ---- load W slice into registers, packed as f32x2 pairs ----
    const int grow = (row >> 5) * 256 + (int)rank * 32 + (row & 31);
    unsigned long long wq[16];
#pragma unroll
    for (int i = 0; i < 8; i++) {
        float4 v = *(const float4*)&W_hh[(size_t)grow * H_ + k8 * 32 + i * 4];
        wq[2 * i + 0] = packf2(v.x, v.y);
        wq[2 * i + 1] = packf2(v.z, v.w);
    }

    // ---- zero h buffer 0 ----
    for (int i = tid; i < 4 * 256; i += REC_THREADS) ((float*)hb[0])[i] = 0.f;

    // ---- gate-thread constants (threads 0..127: b = tid>>5, j = tid&31) ----
    const int gb  = tid >> 5;
    const int gj  = tid & 31;
    const int col = (int)rank * 32 + gj;
    const int myb = b0 + gb;
    const int swi = hswiz(col);        // swizzled index within a batch row
    float bhr = 0.f, bhz = 0.f, bhn = 0.f;
    int mylen = 0;
    if (tid < 128) {
        bhr = b_hh[col];
        bhz = b_hh[256 + col];
        bhn = b_hh[512 + col];
        mylen = lengths[myb];
    }
    const int Tmax = max(max(__ldg(&lengths[b0]),     __ldg(&lengths[b0 + 1])),
                         max(__ldg(&lengths[b0 + 2]), __ldg(&lengths[b0 + 3])));

    __syncthreads();

    for (int t = 0; t < Tmax; t++) {
        const int cur = t & 1, nxt = cur ^ 1;

        // prefetch gi + attention weight (consumed after matvec)
        float gir = 0.f, giz = 0.f, gin = 0.f, wt = 0.f;
        if (tid < 128) {
            const size_t base = ((size_t)t * B_ + myb) * G3_;
            gir = __ldg(&g_Gi[base + col]);
            giz = __ldg(&g_Gi[base + 256 + col]);
            gin = __ldg(&g_Gi[base + 512 + col]);
            wt  = __ldg(&att[(size_t)myb * T_ + t]);
        }

        // ---- matvec: row dot over k-eighth for 4 batches, packed f32x2 ----
        const char* hbase = (const char*)&hb[cur][0][k8 * 32];
        unsigned long long a0 = 0ull, a1 = 0ull, a2 = 0ull, a3 = 0ull;
#pragma unroll
        for (int i = 0; i < 8; i++) {
            const int s = (i + k8) & 7;
            double2 h0 = ((const double2*)(hbase + 0 * 1024))[s];
            double2 h1 = ((const double2*)(hbase + 1 * 1024))[s];
            double2 h2 = ((const double2*)(hbase + 2 * 1024))[s];
            double2 h3 = ((const double2*)(hbase + 3 * 1024))[s];
            a0 = fma2(wq[2*i], __double_as_longlong(h0.x), a0);
            a1 = fma2(wq[2*i], __double_as_longlong(h1.x), a1);
            a2 = fma2(wq[2*i], __double_as_longlong(h2.x), a2);
            a3 = fma2(wq[2*i], __double_as_longlong(h3.x), a3);
            a0 = fma2(wq[2*i+1], __double_as_longlong(h0.y), a0);
            a1 = fma2(wq[2*i+1], __double_as_longlong(h1.y), a1);
            a2 = fma2(wq[2*i+1], __double_as_longlong(h2.y), a2);
            a3 = fma2(wq[2*i+1], __double_as_longlong(h3.y), a3);
        }
        float s0 = unpack_sum(a0), s1 = unpack_sum(a1);
        float s2 = unpack_sum(a2), s3 = unpack_sum(a3);
#pragma unroll
        for (int ofs = 1; ofs < 8; ofs <<= 1) {
            s0 += __shfl_xor_sync(0xffffffffu, s0, ofs);
            s1 += __shfl_xor_sync(0xffffffffu, s1, ofs);
            s2 += __shfl_xor_sync(0xffffffffu, s2, ofs);
            s3 += __shfl_xor_sync(0xffffffffu, s3, ofs);
        }
        if (k8 == 0) ghsh[0][row] = s0;
        if (k8 == 1) ghsh[1][row] = s1;
        if (k8 == 2) ghsh[2][row] = s2;
        if (k8 == 3) ghsh[3][row] = s3;
        __syncthreads();

        // ---- gates + DSMEM broadcast of own 32-col slice to all 8 CTAs ----
        if (tid < 128) {
            const float ghr = ghsh[gb][gj];
            const float ghz = ghsh[gb][32 + gj];
            const float ghn = ghsh[gb][64 + gj];
            const float hprev = hb[cur][gb][swi];
            const float r = sigm(gir + ghr + bhr);
            const float z = sigm(giz + ghz + bhz);
            const float n = tanhf(gin + r * (ghn + bhn));
            const float hnew = (1.f - z) * n + z * hprev;
            const float hg   = wt * hnew + (1.f - wt) * hprev;
            const float hv   = (t < mylen) ? hg : hprev;

            uint32_t laddr = (uint32_t)__cvta_generic_to_shared(
                (const void*)&hb[nxt][gb][swi]);
#pragma unroll
            for (int rdst = 0; rdst < 8; rdst++) {
                uint32_t raddr;
                asm volatile("mapa.shared::cluster.u32 %0, %1, %2;"
                             : "=r"(raddr) : "r"(laddr), "r"(rdst));
                asm volatile("st.shared::cluster.f32 [%0], %1;"
                             :: "r"(raddr), "f"(hv) : "memory");
            }
        }

        // one cluster barrier per step (orders DSMEM stores, full rendezvous)
        asm volatile("barrier.cluster.arrive.aligned;" ::: "memory");
        asm volatile("barrier.cluster.wait.aligned;" ::: "memory");
    }

    if (tid < 128) out[(size_t)myb * H_ + col] = hb[Tmax & 1][gb][swi];
}

// ======================= launch =======================
extern "C" void kernel_launch(void* const* d_in, const int* in_sizes, int n_in,
                              void* d_out, int out_size)
{
    const float* x       = (const float*)d_in[0];
    const float* att     = (const float*)d_in[1];
    const int*   lengths = (const int*)  d_in[2];
    const float* W_ih    = (const float*)d_in[3];
    const float* W_hh    = (const float*)d_in[4];
    const float* b_ih    = (const float*)d_in[5];
    const float* b_hh    = (const float*)d_in[6];
    float* out = (float*)d_out;
    (void)in_sizes; (void)n_in; (void)out_size;

    dim3 ggrid((B_ * T_) / BM, G3_ / BN);
    gi_gemm<<<ggrid, 256>>>(x, W_ih, b_ih, lengths);
    gru_rec<<<128, REC_THREADS>>>(att, lengths, W_hh, b_hh, out);
}